// round 11
// baseline (speedup 1.0000x reference)
#include <cuda_runtime.h>
#include <cuda_bf16.h>
#include <cstdint>

// Problem constants
#define N_OBJ     32
#define N_GROUPS  4960      // C(32,3)
#define N_FILT    16
#define REL_DIM   16
#define BATCH     32
#define N_Q       512
#define FDIM      144       // 3*3*16
#define M_ROWS    512       // BATCH * N_FILT

// Split-bf16 segmented-K GEMM geometry
#define SEG       4992
#define KPAD      14976     // 3 * SEG = 234 * 64
#define KBLK      234
#define SPLITZ    9
#define CHUNKS    26        // KBLK / SPLITZ
#define CTA_M     128
#define CTA_N     128
#define BK        64
#define STAGES    3
#define STAGE_BYTES 32768
#define SMEM_TOTAL (STAGES * STAGE_BYTES)

// Scratch (no cudaMalloc allowed)
__device__ int            g_idxp[N_GROUPS];            // packed i|j<<8|k<<16
__device__ __nv_bfloat16  A3[(size_t)M_ROWS * KPAD];   // [m][k'] k'-major
__device__ __nv_bfloat16  B3[(size_t)N_Q * KPAD];      // [g][k'] k'-major
__device__ float          g_part[(size_t)SPLITZ * M_ROWS * N_Q];
// P[b][pos][o1][o2][f]: per-pair per-position filter responses (18.9 MB)
__device__ float          Ptab[(size_t)BATCH * 9 * N_OBJ * N_OBJ * N_FILT];

// ---------------------------------------------------------------------------
// PTX helpers (family-safe: sm_80-era mma.sync / ldmatrix / cp.async)
// ---------------------------------------------------------------------------
__device__ __forceinline__ uint32_t smem_u32(const void* p) {
    uint32_t a;
    asm("{ .reg .u64 t; cvta.to.shared.u64 t, %1; cvt.u32.u64 %0, t; }"
        : "=r"(a) : "l"(p));
    return a;
}

__device__ __forceinline__ void cp_async16(uint32_t dst, const void* src) {
    asm volatile("cp.async.cg.shared.global [%0], [%1], 16;\n"
                 :: "r"(dst), "l"(src) : "memory");
}
#define CP_COMMIT() asm volatile("cp.async.commit_group;\n" ::: "memory")
#define CP_WAIT1()  asm volatile("cp.async.wait_group 1;\n" ::: "memory")
#define CP_WAIT0()  asm volatile("cp.async.wait_group 0;\n" ::: "memory")

__device__ __forceinline__ void ldsm_x4(uint32_t* r, uint32_t addr) {
    asm volatile("ldmatrix.sync.aligned.m8n8.x4.shared.b16 {%0,%1,%2,%3}, [%4];\n"
                 : "=r"(r[0]), "=r"(r[1]), "=r"(r[2]), "=r"(r[3]) : "r"(addr));
}

__device__ __forceinline__ void mma_16816(float* c, const uint32_t* a, const uint32_t* b) {
    asm volatile("mma.sync.aligned.m16n8k16.row.col.f32.bf16.bf16.f32 "
                 "{%0,%1,%2,%3}, {%4,%5,%6,%7}, {%8,%9}, {%0,%1,%2,%3};\n"
                 : "+f"(c[0]), "+f"(c[1]), "+f"(c[2]), "+f"(c[3])
                 : "r"(a[0]), "r"(a[1]), "r"(a[2]), "r"(a[3]), "r"(b[0]), "r"(b[1]));
}

// FFMA-only exp (x <= 0 expected; clamps at -87).
__device__ __forceinline__ float fast_exp(float x) {
    x = fmaxf(x, -87.0f);
    float t = x * 1.4426950408889634f;
    int ri = __float2int_rn(t);
    float f = t - (float)ri;
    float p = 1.8775767e-3f;
    p = fmaf(p, f, 8.9893397e-3f);
    p = fmaf(p, f, 5.5826318e-2f);
    p = fmaf(p, f, 2.4015361e-1f);
    p = fmaf(p, f, 6.9315308e-1f);
    p = fmaf(p, f, 1.0f);
    return p * __int_as_float((ri + 127) << 23);
}

// ---------------------------------------------------------------------------
// Kernel 0: unrank C(32,3) + zero segment padding of A3/B3 + build P table.
// P[b][pos][o1][o2][f] = sum_d inputs[b,o1,o2,d] * filt[f,pos,d]
// ---------------------------------------------------------------------------
#define PAD_PER_ROW (3 * (SEG - N_GROUPS))    // 96
#define PAD_WORK    (512 * PAD_PER_ROW)       // 49152
#define PTAB_THREADS (BATCH * 9 * N_OBJ * N_OBJ)   // 294912
__global__ void k_init(const float* __restrict__ inputs,
                       const float* __restrict__ filters) {
    __shared__ __align__(16) float filt_t[9 * 16 * 16];   // [pos][d][f]
    int tid = threadIdx.x;
    for (int t = tid; t < N_FILT * FDIM; t += blockDim.x) {
        int f = t / FDIM;
        int rem = t - f * FDIM;
        int pos = rem >> 4;
        int d = rem & 15;
        filt_t[pos * 256 + d * 16 + f] = filters[t];
    }
    __syncthreads();

    int n = blockIdx.x * blockDim.x + tid;

    if (n < N_GROUPS) {
        int rem = n, i = 0;
        for (; i < 30; i++) {
            int c = (31 - i) * (30 - i) / 2;
            if (rem < c) break;
            rem -= c;
        }
        int j = i + 1;
        for (; j < 31; j++) {
            int c = 31 - j;
            if (rem < c) break;
            rem -= c;
        }
        int k = j + 1 + rem;
        g_idxp[n] = i | (j << 8) | (k << 16);
    }
    if (n < PAD_WORK) {
        int r = n / PAD_PER_ROW;
        int q = n % PAD_PER_ROW;
        int seg = q / (SEG - N_GROUPS);
        int off = q % (SEG - N_GROUPS);
        size_t c = (size_t)seg * SEG + N_GROUPS + off;
        __nv_bfloat16 z = __float2bfloat16(0.f);
        A3[(size_t)r * KPAD + c] = z;
        B3[(size_t)r * KPAD + c] = z;
    }
    if (n < PTAB_THREADS) {
        int bp = n >> 10;            // b*9 + pos
        int o12 = n & 1023;          // o1*32 + o2
        int b = bp / 9;
        int pos = bp - b * 9;

        const float4* ip = reinterpret_cast<const float4*>(
            inputs + ((size_t)(b * 1024 + o12)) * REL_DIM);
        float4 v0 = ip[0], v1 = ip[1], v2 = ip[2], v3 = ip[3];
        float xs[16] = {v0.x, v0.y, v0.z, v0.w, v1.x, v1.y, v1.z, v1.w,
                        v2.x, v2.y, v2.z, v2.w, v3.x, v3.y, v3.z, v3.w};

        float acc[16];
#pragma unroll
        for (int f = 0; f < 16; f++) acc[f] = 0.f;
        const float4* ft = reinterpret_cast<const float4*>(&filt_t[pos * 256]);
#pragma unroll
        for (int d = 0; d < 16; d++) {
            float x = xs[d];
            float4 f0 = ft[d * 4 + 0];
            float4 f1 = ft[d * 4 + 1];
            float4 f2 = ft[d * 4 + 2];
            float4 f3 = ft[d * 4 + 3];
            acc[0]  = fmaf(x, f0.x, acc[0]);  acc[1]  = fmaf(x, f0.y, acc[1]);
            acc[2]  = fmaf(x, f0.z, acc[2]);  acc[3]  = fmaf(x, f0.w, acc[3]);
            acc[4]  = fmaf(x, f1.x, acc[4]);  acc[5]  = fmaf(x, f1.y, acc[5]);
            acc[6]  = fmaf(x, f1.z, acc[6]);  acc[7]  = fmaf(x, f1.w, acc[7]);
            acc[8]  = fmaf(x, f2.x, acc[8]);  acc[9]  = fmaf(x, f2.y, acc[9]);
            acc[10] = fmaf(x, f2.z, acc[10]); acc[11] = fmaf(x, f2.w, acc[11]);
            acc[12] = fmaf(x, f3.x, acc[12]); acc[13] = fmaf(x, f3.y, acc[13]);
            acc[14] = fmaf(x, f3.z, acc[14]); acc[15] = fmaf(x, f3.w, acc[15]);
        }
        float4* dst = reinterpret_cast<float4*>(Ptab + (size_t)n * 16);
        dst[0] = make_float4(acc[0],  acc[1],  acc[2],  acc[3]);
        dst[1] = make_float4(acc[4],  acc[5],  acc[6],  acc[7]);
        dst[2] = make_float4(acc[8],  acc[9],  acc[10], acc[11]);
        dst[3] = make_float4(acc[12], acc[13], acc[14], acc[15]);
    }
}

// ---------------------------------------------------------------------------
// Kernel 1: rel_conv via P-table gather: acc[f] = sum_pos P[b][pos][oi][oj][f].
// 9 float4-quad gathers + 128 FADD per (b,n)  (was 2304 FMA).
// Split-bf16 A3 rows (segmented: ah | ah | al), coalesced stores.
// ---------------------------------------------------------------------------
__global__ void k_relconv() {
    int tid = threadIdx.x;
    int n = blockIdx.x * blockDim.x + tid;
    int b = blockIdx.y;
    if (n >= N_GROUPS) return;

    int pk = g_idxp[n];
    int obj[3] = {pk & 255, (pk >> 8) & 255, pk >> 16};

    float4 a0 = make_float4(0.f, 0.f, 0.f, 0.f);
    float4 a1 = a0, a2 = a0, a3 = a0;

#pragma unroll
    for (int ii = 0; ii < 3; ii++) {
#pragma unroll
        for (int jj = 0; jj < 3; jj++) {
            int pos = ii * 3 + jj;
            const float4* pp = reinterpret_cast<const float4*>(
                Ptab + (size_t)(((b * 9 + pos) * 32 + obj[ii]) * 32 + obj[jj]) * 16);
            float4 p0 = pp[0], p1 = pp[1], p2 = pp[2], p3 = pp[3];
            a0.x += p0.x; a0.y += p0.y; a0.z += p0.z; a0.w += p0.w;
            a1.x += p1.x; a1.y += p1.y; a1.z += p1.z; a1.w += p1.w;
            a2.x += p2.x; a2.y += p2.y; a2.z += p2.z; a2.w += p2.w;
            a3.x += p3.x; a3.y += p3.y; a3.z += p3.z; a3.w += p3.w;
        }
    }

    float acc[16] = {a0.x, a0.y, a0.z, a0.w, a1.x, a1.y, a1.z, a1.w,
                     a2.x, a2.y, a2.z, a2.w, a3.x, a3.y, a3.z, a3.w};
#pragma unroll
    for (int f = 0; f < 16; f++) {
        __nv_bfloat16 hi = __float2bfloat16(acc[f]);
        __nv_bfloat16 lo = __float2bfloat16(acc[f] - __bfloat162float(hi));
        size_t row = (size_t)(b * 16 + f) * KPAD;
        A3[row + n]           = hi;
        A3[row + SEG + n]     = hi;
        A3[row + 2 * SEG + n] = lo;
    }
}

// ---------------------------------------------------------------------------
// Kernel 2: per-query softplus-product softmax -> split-bf16 B3 rows
// (segmented: bh | bl | bh).  Coalesced stores; exp on FMA pipe.
// ---------------------------------------------------------------------------
__global__ void k_weights(const float* __restrict__ logits) {
    int g = blockIdx.x;
    __shared__ float sp_s[N_OBJ];
    __shared__ float w_s[N_GROUPS];
    __shared__ float red_s[8];

    int tid = threadIdx.x;
    if (tid < N_OBJ) {
        float x = logits[g * N_OBJ + tid];
        sp_s[tid] = fmaxf(x, 0.f) + log1pf(expf(-fabsf(x)));
    }
    __syncthreads();

    float lmax = -1e30f;
    for (int n = tid; n < N_GROUPS; n += 256) {
        int pk = g_idxp[n];
        float w = sp_s[pk & 255] * sp_s[(pk >> 8) & 255] * sp_s[pk >> 16];
        w_s[n] = w;
        lmax = fmaxf(lmax, w);
    }
#pragma unroll
    for (int o = 16; o > 0; o >>= 1)
        lmax = fmaxf(lmax, __shfl_xor_sync(0xffffffffu, lmax, o));
    if ((tid & 31) == 0) red_s[tid >> 5] = lmax;
    __syncthreads();
    float bmax = red_s[0];
#pragma unroll
    for (int r = 1; r < 8; r++) bmax = fmaxf(bmax, red_s[r]);

    float lsum = 0.f;
    for (int n = tid; n < N_GROUPS; n += 256) {
        float e = fast_exp(w_s[n] - bmax);
        w_s[n] = e;
        lsum += e;
    }
#pragma unroll
    for (int o = 16; o > 0; o >>= 1)
        lsum += __shfl_xor_sync(0xffffffffu, lsum, o);
    __syncthreads();
    if ((tid & 31) == 0) red_s[tid >> 5] = lsum;
    __syncthreads();
    float bsum = 0.f;
#pragma unroll
    for (int r = 0; r < 8; r++) bsum += red_s[r];
    float inv = 1.f / bsum;

    size_t row = (size_t)g * KPAD;
    for (int n = tid; n < N_GROUPS; n += 256) {
        float v = w_s[n] * inv;
        __nv_bfloat16 hi = __float2bfloat16(v);
        __nv_bfloat16 lo = __float2bfloat16(v - __bfloat162float(hi));
        B3[row + n]           = hi;
        B3[row + SEG + n]     = lo;
        B3[row + 2 * SEG + n] = hi;
    }
}

// ---------------------------------------------------------------------------
// Kernel 3: HMMA bf16 GEMM  part[z][m][g] = sum_{k' in split} A3[m][k']*B3[g][k']
// CTA 128x128, warp 32x64, BK=64 swizzled, cp.async 3-stage, split-K Z=9.
// (Exact known-good 25.5us configuration.)
// ---------------------------------------------------------------------------
__global__ void __launch_bounds__(256) k_mma() {
    extern __shared__ char smem[];
    const uint32_t sbase = smem_u32(smem);
    int tid = threadIdx.x;
    int lane = tid & 31;
    int wid = tid >> 5;
    int wm = wid & 3;
    int wn = wid >> 2;
    int m0 = blockIdx.y * CTA_M;
    int n0 = blockIdx.x * CTA_N;
    int kb0 = blockIdx.z * CHUNKS;

    int seg_r[4], seg_c[4];
#pragma unroll
    for (int i = 0; i < 4; i++) {
        int seg = tid + i * 256;
        seg_r[i] = seg >> 3;
        seg_c[i] = seg & 7;
    }

    float acc[2][8][4];
#pragma unroll
    for (int mt = 0; mt < 2; mt++)
#pragma unroll
        for (int nt = 0; nt < 8; nt++)
#pragma unroll
            for (int q = 0; q < 4; q++) acc[mt][nt][q] = 0.f;

#pragma unroll
    for (int pc = 0; pc < 2; pc++) {
        uint32_t abase = sbase + pc * STAGE_BYTES;
        uint32_t bbase = abase + 16384;
        size_t kelem = (size_t)(kb0 + pc) * BK;
#pragma unroll
        for (int i = 0; i < 4; i++) {
            int r = seg_r[i], c = seg_c[i];
            uint32_t swo = (uint32_t)(r * 128 + ((c ^ (r & 7)) << 4));
            cp_async16(abase + swo, A3 + (size_t)(m0 + r) * KPAD + kelem + c * 8);
            cp_async16(bbase + swo, B3 + (size_t)(n0 + r) * KPAD + kelem + c * 8);
        }
        CP_COMMIT();
    }

    for (int kc = 0; kc < CHUNKS; kc++) {
        int stg = kc % STAGES;
        CP_WAIT1();
        __syncthreads();

        if (kc + 2 < CHUNKS) {
            int ps = (kc + 2) % STAGES;
            uint32_t abase = sbase + ps * STAGE_BYTES;
            uint32_t bbase = abase + 16384;
            size_t kelem = (size_t)(kb0 + kc + 2) * BK;
#pragma unroll
            for (int i = 0; i < 4; i++) {
                int r = seg_r[i], c = seg_c[i];
                uint32_t swo = (uint32_t)(r * 128 + ((c ^ (r & 7)) << 4));
                cp_async16(abase + swo, A3 + (size_t)(m0 + r) * KPAD + kelem + c * 8);
                cp_async16(bbase + swo, B3 + (size_t)(n0 + r) * KPAD + kelem + c * 8);
            }
        }
        CP_COMMIT();

        uint32_t abase = sbase + stg * STAGE_BYTES;
        uint32_t bbase = abase + 16384;
#pragma unroll
        for (int ks = 0; ks < 4; ks++) {
            int t = lane >> 3, rw = lane & 7;
            uint32_t a[2][4];
#pragma unroll
            for (int mt = 0; mt < 2; mt++) {
                int m = wm * 32 + mt * 16 + ((t & 1) ? 8 : 0) + rw;
                int c = ks * 2 + (t >> 1);
                ldsm_x4(a[mt], abase + m * 128 + ((c ^ (m & 7)) << 4));
            }
            uint32_t b[8][2];
#pragma unroll
            for (int np = 0; np < 4; np++) {
                int n = wn * 64 + np * 16 + ((t & 2) ? 8 : 0) + rw;
                int c = ks * 2 + (t & 1);
                uint32_t r4[4];
                ldsm_x4(r4, bbase + n * 128 + ((c ^ (n & 7)) << 4));
                b[np * 2 + 0][0] = r4[0]; b[np * 2 + 0][1] = r4[1];
                b[np * 2 + 1][0] = r4[2]; b[np * 2 + 1][1] = r4[3];
            }
#pragma unroll
            for (int mt = 0; mt < 2; mt++)
#pragma unroll
                for (int nt = 0; nt < 8; nt++)
                    mma_16816(acc[mt][nt], a[mt], b[nt]);
        }
    }
    CP_WAIT0();

    float* base = g_part + (size_t)blockIdx.z * (M_ROWS * N_Q);
    int gr = lane >> 2, gc = (lane & 3) * 2;
#pragma unroll
    for (int mt = 0; mt < 2; mt++) {
#pragma unroll
        for (int nt = 0; nt < 8; nt++) {
            int row = m0 + wm * 32 + mt * 16 + gr;
            int col = n0 + wn * 64 + nt * 8 + gc;
            *reinterpret_cast<float2*>(&base[(size_t)row * N_Q + col]) =
                make_float2(acc[mt][nt][0], acc[mt][nt][1]);
            *reinterpret_cast<float2*>(&base[(size_t)(row + 8) * N_Q + col]) =
                make_float2(acc[mt][nt][2], acc[mt][nt][3]);
        }
    }
}

// ---------------------------------------------------------------------------
// Kernel 4: reduce split-K partials; transpose (b,f)-rows into out[b,g,f]
// ---------------------------------------------------------------------------
__global__ void k_reduce(float* __restrict__ out) {
    int m = blockIdx.x;          // 0..511  (= b*16 + f)
    int gcol = threadIdx.x;      // 0..511
    float s = 0.f;
#pragma unroll
    for (int z = 0; z < SPLITZ; z++)
        s += g_part[(size_t)z * (M_ROWS * N_Q) + (size_t)m * N_Q + gcol];
    out[((size_t)(m >> 4) * N_Q + gcol) * N_FILT + (m & 15)] = s;
}

// ---------------------------------------------------------------------------
extern "C" void kernel_launch(void* const* d_in, const int* in_sizes, int n_in,
                              void* d_out, int out_size) {
    const float* inputs  = (const float*)d_in[0];   // (32,32,32,16) fp32
    const float* logits  = (const float*)d_in[1];   // (512,32) fp32
    const float* filters = (const float*)d_in[2];   // (16,3,3,16) fp32
    float* out = (float*)d_out;                     // (32,512,16) fp32
    (void)in_sizes; (void)n_in; (void)out_size;

    cudaFuncSetAttribute(k_mma, cudaFuncAttributeMaxDynamicSharedMemorySize, SMEM_TOTAL);

    k_init<<<(PTAB_THREADS + 255) / 256, 256>>>(inputs, filters);
    k_relconv<<<dim3((N_GROUPS + 127) / 128, BATCH), 128>>>();
    k_weights<<<N_Q, 256>>>(logits);
    k_mma<<<dim3(N_Q / CTA_N, M_ROWS / CTA_M, SPLITZ), 256, SMEM_TOTAL>>>();
    k_reduce<<<M_ROWS, N_Q>>>(out);
}

// round 14
// speedup vs baseline: 1.2443x; 1.2443x over previous
#include <cuda_runtime.h>
#include <cuda_bf16.h>
#include <cstdint>

// Problem constants
#define N_OBJ     32
#define N_GROUPS  4960      // C(32,3)
#define N_FILT    16
#define REL_DIM   16
#define BATCH     32
#define N_Q       512
#define FDIM      144       // 3*3*16
#define M_ROWS    512       // BATCH * N_FILT

// Split-bf16 segmented-K GEMM geometry
#define SEG       4992
#define KPAD      14976     // 3 * SEG = 234 * 64
#define KBLK      234
#define SPLITZ    9
#define CHUNKS    26        // KBLK / SPLITZ
#define CTA_M     128
#define CTA_N     128
#define BK        64
#define STAGES    3
#define STAGE_BYTES 32768
#define SMEM_TOTAL (STAGES * STAGE_BYTES)

// Scratch (no cudaMalloc allowed)
__device__ int            g_idxp[N_GROUPS];            // packed i|j<<8|k<<16
__device__ __nv_bfloat16  A3[(size_t)M_ROWS * KPAD];   // [m][k'] k'-major
__device__ __nv_bfloat16  B3[(size_t)N_Q * KPAD];      // [g][k'] k'-major
__device__ float          g_part[(size_t)SPLITZ * M_ROWS * N_Q];

// ---------------------------------------------------------------------------
// PTX helpers (family-safe: sm_80-era mma.sync / ldmatrix / cp.async)
// ---------------------------------------------------------------------------
__device__ __forceinline__ uint32_t smem_u32(const void* p) {
    uint32_t a;
    asm("{ .reg .u64 t; cvta.to.shared.u64 t, %1; cvt.u32.u64 %0, t; }"
        : "=r"(a) : "l"(p));
    return a;
}

__device__ __forceinline__ void cp_async16(uint32_t dst, const void* src) {
    asm volatile("cp.async.cg.shared.global [%0], [%1], 16;\n"
                 :: "r"(dst), "l"(src) : "memory");
}
#define CP_COMMIT() asm volatile("cp.async.commit_group;\n" ::: "memory")
#define CP_WAIT1()  asm volatile("cp.async.wait_group 1;\n" ::: "memory")
#define CP_WAIT0()  asm volatile("cp.async.wait_group 0;\n" ::: "memory")

__device__ __forceinline__ void ldsm_x4(uint32_t* r, uint32_t addr) {
    asm volatile("ldmatrix.sync.aligned.m8n8.x4.shared.b16 {%0,%1,%2,%3}, [%4];\n"
                 : "=r"(r[0]), "=r"(r[1]), "=r"(r[2]), "=r"(r[3]) : "r"(addr));
}

__device__ __forceinline__ void mma_16816(float* c, const uint32_t* a, const uint32_t* b) {
    asm volatile("mma.sync.aligned.m16n8k16.row.col.f32.bf16.bf16.f32 "
                 "{%0,%1,%2,%3}, {%4,%5,%6,%7}, {%8,%9}, {%0,%1,%2,%3};\n"
                 : "+f"(c[0]), "+f"(c[1]), "+f"(c[2]), "+f"(c[3])
                 : "r"(a[0]), "r"(a[1]), "r"(a[2]), "r"(a[3]), "r"(b[0]), "r"(b[1]));
}

// FFMA-only exp (x <= 0 expected; clamps at -87).
__device__ __forceinline__ float fast_exp(float x) {
    x = fmaxf(x, -87.0f);
    float t = x * 1.4426950408889634f;
    int ri = __float2int_rn(t);
    float f = t - (float)ri;
    float p = 1.8775767e-3f;
    p = fmaf(p, f, 8.9893397e-3f);
    p = fmaf(p, f, 5.5826318e-2f);
    p = fmaf(p, f, 2.4015361e-1f);
    p = fmaf(p, f, 6.9315308e-1f);
    p = fmaf(p, f, 1.0f);
    return p * __int_as_float((ri + 127) << 23);
}

// ---------------------------------------------------------------------------
// Kernel 0: unrank C(32,3) + zero segment padding of A3/B3
// ---------------------------------------------------------------------------
#define PAD_PER_ROW (3 * (SEG - N_GROUPS))    // 96
#define PAD_WORK    (512 * PAD_PER_ROW)       // 49152
__global__ void k_init() {
    int n = blockIdx.x * blockDim.x + threadIdx.x;
    if (n < N_GROUPS) {
        int rem = n, i = 0;
        for (; i < 30; i++) {
            int c = (31 - i) * (30 - i) / 2;
            if (rem < c) break;
            rem -= c;
        }
        int j = i + 1;
        for (; j < 31; j++) {
            int c = 31 - j;
            if (rem < c) break;
            rem -= c;
        }
        int k = j + 1 + rem;
        g_idxp[n] = i | (j << 8) | (k << 16);
    }
    if (n < PAD_WORK) {
        int r = n / PAD_PER_ROW;
        int q = n % PAD_PER_ROW;
        int seg = q / (SEG - N_GROUPS);
        int off = q % (SEG - N_GROUPS);
        size_t c = (size_t)seg * SEG + N_GROUPS + off;
        __nv_bfloat16 z = __float2bfloat16(0.f);
        A3[(size_t)r * KPAD + c] = z;
        B3[(size_t)r * KPAD + c] = z;
    }
}

// ---------------------------------------------------------------------------
// Kernel 1 (fused): grid-partitioned roles.
//   blocks [0, 640):   rel_conv -> split-bf16 A3 rows (ah | ah | al)
//   blocks [640, 1152): softplus-product softmax -> split-bf16 B3 rows (bh|bl|bh)
// Independent outputs; fusing saves a launch tail and overlaps the FFMA-bound
// relconv blocks with the LSU/ALU-bound weights blocks across SMs.
// ---------------------------------------------------------------------------
#define RC_PER_B   20      // ceil(4960/256)
#define RC_BLOCKS  (RC_PER_B * BATCH)   // 640
#define FUSED_BLOCKS (RC_BLOCKS + N_Q)  // 1152

__global__ void __launch_bounds__(256) k_fused(const float* __restrict__ inputs,
                                               const float* __restrict__ filters,
                                               const float* __restrict__ logits) {
    __shared__ __align__(16) float sh[5000];   // union: filt_t(2304) | weights(5000)
    int tid = threadIdx.x;
    int blk = blockIdx.x;

    if (blk < RC_BLOCKS) {
        // ---------------- rel_conv role ----------------
        float* filt_t = sh;                    // [pos][d][f] = 9*16*16
        for (int t = tid; t < N_FILT * FDIM; t += 256) {
            int f = t / FDIM;
            int rem = t - f * FDIM;
            int pos = rem >> 4;
            int d = rem & 15;
            filt_t[pos * 256 + d * 16 + f] = filters[t];
        }
        __syncthreads();

        int b = blk / RC_PER_B;
        int n = (blk - b * RC_PER_B) * 256 + tid;
        if (n >= N_GROUPS) return;

        int pk = g_idxp[n];
        int obj[3] = {pk & 255, (pk >> 8) & 255, pk >> 16};
        const float* base = inputs + (size_t)b * N_OBJ * N_OBJ * REL_DIM;

        float acc[16];
#pragma unroll
        for (int f = 0; f < 16; f++) acc[f] = 0.f;

#pragma unroll
        for (int ii = 0; ii < 3; ii++) {
#pragma unroll
            for (int jj = 0; jj < 3; jj++) {
                const float4* p = reinterpret_cast<const float4*>(
                    base + (obj[ii] * N_OBJ + obj[jj]) * REL_DIM);
                float4 v0 = p[0], v1 = p[1], v2 = p[2], v3 = p[3];
                float xs[16] = {v0.x, v0.y, v0.z, v0.w, v1.x, v1.y, v1.z, v1.w,
                                v2.x, v2.y, v2.z, v2.w, v3.x, v3.y, v3.z, v3.w};
                const float4* ft = reinterpret_cast<const float4*>(&filt_t[(ii * 3 + jj) * 256]);
#pragma unroll
                for (int d = 0; d < 16; d++) {
                    float x = xs[d];
                    float4 f0 = ft[d * 4 + 0];
                    float4 f1 = ft[d * 4 + 1];
                    float4 f2 = ft[d * 4 + 2];
                    float4 f3 = ft[d * 4 + 3];
                    acc[0]  = fmaf(x, f0.x, acc[0]);  acc[1]  = fmaf(x, f0.y, acc[1]);
                    acc[2]  = fmaf(x, f0.z, acc[2]);  acc[3]  = fmaf(x, f0.w, acc[3]);
                    acc[4]  = fmaf(x, f1.x, acc[4]);  acc[5]  = fmaf(x, f1.y, acc[5]);
                    acc[6]  = fmaf(x, f1.z, acc[6]);  acc[7]  = fmaf(x, f1.w, acc[7]);
                    acc[8]  = fmaf(x, f2.x, acc[8]);  acc[9]  = fmaf(x, f2.y, acc[9]);
                    acc[10] = fmaf(x, f2.z, acc[10]); acc[11] = fmaf(x, f2.w, acc[11]);
                    acc[12] = fmaf(x, f3.x, acc[12]); acc[13] = fmaf(x, f3.y, acc[13]);
                    acc[14] = fmaf(x, f3.z, acc[14]); acc[15] = fmaf(x, f3.w, acc[15]);
                }
            }
        }
#pragma unroll
        for (int f = 0; f < 16; f++) {
            __nv_bfloat16 hi = __float2bfloat16(acc[f]);
            __nv_bfloat16 lo = __float2bfloat16(acc[f] - __bfloat162float(hi));
            size_t row = (size_t)(b * 16 + f) * KPAD;
            A3[row + n]           = hi;
            A3[row + SEG + n]     = hi;
            A3[row + 2 * SEG + n] = lo;
        }
    } else {
        // ---------------- weights role ----------------
        int g = blk - RC_BLOCKS;
        float* sp_s  = sh;          // 32
        float* w_s   = sh + 32;     // 4960
        float* red_s = sh + 4992;   // 8

        if (tid < N_OBJ) {
            float x = logits[g * N_OBJ + tid];
            sp_s[tid] = fmaxf(x, 0.f) + log1pf(expf(-fabsf(x)));
        }
        __syncthreads();

        float lmax = -1e30f;
        for (int n = tid; n < N_GROUPS; n += 256) {
            int pk = g_idxp[n];
            float w = sp_s[pk & 255] * sp_s[(pk >> 8) & 255] * sp_s[pk >> 16];
            w_s[n] = w;
            lmax = fmaxf(lmax, w);
        }
#pragma unroll
        for (int o = 16; o > 0; o >>= 1)
            lmax = fmaxf(lmax, __shfl_xor_sync(0xffffffffu, lmax, o));
        if ((tid & 31) == 0) red_s[tid >> 5] = lmax;
        __syncthreads();
        float bmax = red_s[0];
#pragma unroll
        for (int r = 1; r < 8; r++) bmax = fmaxf(bmax, red_s[r]);

        float lsum = 0.f;
        for (int n = tid; n < N_GROUPS; n += 256) {
            float e = fast_exp(w_s[n] - bmax);
            w_s[n] = e;
            lsum += e;
        }
#pragma unroll
        for (int o = 16; o > 0; o >>= 1)
            lsum += __shfl_xor_sync(0xffffffffu, lsum, o);
        __syncthreads();
        if ((tid & 31) == 0) red_s[tid >> 5] = lsum;
        __syncthreads();
        float bsum = 0.f;
#pragma unroll
        for (int r = 0; r < 8; r++) bsum += red_s[r];
        float inv = 1.f / bsum;

        size_t row = (size_t)g * KPAD;
        for (int n = tid; n < N_GROUPS; n += 256) {
            float v = w_s[n] * inv;
            __nv_bfloat16 hi = __float2bfloat16(v);
            __nv_bfloat16 lo = __float2bfloat16(v - __bfloat162float(hi));
            B3[row + n]           = hi;
            B3[row + SEG + n]     = lo;
            B3[row + 2 * SEG + n] = hi;
        }
    }
}

// ---------------------------------------------------------------------------
// Kernel 3: HMMA bf16 GEMM  part[z][m][g] = sum_{k' in split} A3[m][k']*B3[g][k']
// CTA 128x128, warp 32x64, BK=64 swizzled, cp.async 3-stage, split-K Z=9.
// (Exact known-good 25.5us configuration.)
// ---------------------------------------------------------------------------
__global__ void __launch_bounds__(256) k_mma() {
    extern __shared__ char smem[];
    const uint32_t sbase = smem_u32(smem);
    int tid = threadIdx.x;
    int lane = tid & 31;
    int wid = tid >> 5;
    int wm = wid & 3;
    int wn = wid >> 2;
    int m0 = blockIdx.y * CTA_M;
    int n0 = blockIdx.x * CTA_N;
    int kb0 = blockIdx.z * CHUNKS;

    int seg_r[4], seg_c[4];
#pragma unroll
    for (int i = 0; i < 4; i++) {
        int seg = tid + i * 256;
        seg_r[i] = seg >> 3;
        seg_c[i] = seg & 7;
    }

    float acc[2][8][4];
#pragma unroll
    for (int mt = 0; mt < 2; mt++)
#pragma unroll
        for (int nt = 0; nt < 8; nt++)
#pragma unroll
            for (int q = 0; q < 4; q++) acc[mt][nt][q] = 0.f;

#pragma unroll
    for (int pc = 0; pc < 2; pc++) {
        uint32_t abase = sbase + pc * STAGE_BYTES;
        uint32_t bbase = abase + 16384;
        size_t kelem = (size_t)(kb0 + pc) * BK;
#pragma unroll
        for (int i = 0; i < 4; i++) {
            int r = seg_r[i], c = seg_c[i];
            uint32_t swo = (uint32_t)(r * 128 + ((c ^ (r & 7)) << 4));
            cp_async16(abase + swo, A3 + (size_t)(m0 + r) * KPAD + kelem + c * 8);
            cp_async16(bbase + swo, B3 + (size_t)(n0 + r) * KPAD + kelem + c * 8);
        }
        CP_COMMIT();
    }

    for (int kc = 0; kc < CHUNKS; kc++) {
        int stg = kc % STAGES;
        CP_WAIT1();
        __syncthreads();

        if (kc + 2 < CHUNKS) {
            int ps = (kc + 2) % STAGES;
            uint32_t abase = sbase + ps * STAGE_BYTES;
            uint32_t bbase = abase + 16384;
            size_t kelem = (size_t)(kb0 + kc + 2) * BK;
#pragma unroll
            for (int i = 0; i < 4; i++) {
                int r = seg_r[i], c = seg_c[i];
                uint32_t swo = (uint32_t)(r * 128 + ((c ^ (r & 7)) << 4));
                cp_async16(abase + swo, A3 + (size_t)(m0 + r) * KPAD + kelem + c * 8);
                cp_async16(bbase + swo, B3 + (size_t)(n0 + r) * KPAD + kelem + c * 8);
            }
        }
        CP_COMMIT();

        uint32_t abase = sbase + stg * STAGE_BYTES;
        uint32_t bbase = abase + 16384;
#pragma unroll
        for (int ks = 0; ks < 4; ks++) {
            int t = lane >> 3, rw = lane & 7;
            uint32_t a[2][4];
#pragma unroll
            for (int mt = 0; mt < 2; mt++) {
                int m = wm * 32 + mt * 16 + ((t & 1) ? 8 : 0) + rw;
                int c = ks * 2 + (t >> 1);
                ldsm_x4(a[mt], abase + m * 128 + ((c ^ (m & 7)) << 4));
            }
            uint32_t b[8][2];
#pragma unroll
            for (int np = 0; np < 4; np++) {
                int n = wn * 64 + np * 16 + ((t & 2) ? 8 : 0) + rw;
                int c = ks * 2 + (t & 1);
                uint32_t r4[4];
                ldsm_x4(r4, bbase + n * 128 + ((c ^ (n & 7)) << 4));
                b[np * 2 + 0][0] = r4[0]; b[np * 2 + 0][1] = r4[1];
                b[np * 2 + 1][0] = r4[2]; b[np * 2 + 1][1] = r4[3];
            }
#pragma unroll
            for (int mt = 0; mt < 2; mt++)
#pragma unroll
                for (int nt = 0; nt < 8; nt++)
                    mma_16816(acc[mt][nt], a[mt], b[nt]);
        }
    }
    CP_WAIT0();

    float* base = g_part + (size_t)blockIdx.z * (M_ROWS * N_Q);
    int gr = lane >> 2, gc = (lane & 3) * 2;
#pragma unroll
    for (int mt = 0; mt < 2; mt++) {
#pragma unroll
        for (int nt = 0; nt < 8; nt++) {
            int row = m0 + wm * 32 + mt * 16 + gr;
            int col = n0 + wn * 64 + nt * 8 + gc;
            *reinterpret_cast<float2*>(&base[(size_t)row * N_Q + col]) =
                make_float2(acc[mt][nt][0], acc[mt][nt][1]);
            *reinterpret_cast<float2*>(&base[(size_t)(row + 8) * N_Q + col]) =
                make_float2(acc[mt][nt][2], acc[mt][nt][3]);
        }
    }
}

// ---------------------------------------------------------------------------
// Kernel 4: reduce split-K partials; transpose (b,f)-rows into out[b,g,f]
// ---------------------------------------------------------------------------
__global__ void k_reduce(float* __restrict__ out) {
    int m = blockIdx.x;          // 0..511  (= b*16 + f)
    int gcol = threadIdx.x;      // 0..511
    float s = 0.f;
#pragma unroll
    for (int z = 0; z < SPLITZ; z++)
        s += g_part[(size_t)z * (M_ROWS * N_Q) + (size_t)m * N_Q + gcol];
    out[((size_t)(m >> 4) * N_Q + gcol) * N_FILT + (m & 15)] = s;
}

// ---------------------------------------------------------------------------
extern "C" void kernel_launch(void* const* d_in, const int* in_sizes, int n_in,
                              void* d_out, int out_size) {
    const float* inputs  = (const float*)d_in[0];   // (32,32,32,16) fp32
    const float* logits  = (const float*)d_in[1];   // (512,32) fp32
    const float* filters = (const float*)d_in[2];   // (16,3,3,16) fp32
    float* out = (float*)d_out;                     // (32,512,16) fp32
    (void)in_sizes; (void)n_in; (void)out_size;

    cudaFuncSetAttribute(k_mma, cudaFuncAttributeMaxDynamicSharedMemorySize, SMEM_TOTAL);

    k_init<<<(PAD_WORK + 255) / 256, 256>>>();
    k_fused<<<FUSED_BLOCKS, 256>>>(inputs, filters, logits);
    k_mma<<<dim3(N_Q / CTA_N, M_ROWS / CTA_M, SPLITZ), 256, SMEM_TOTAL>>>();
    k_reduce<<<M_ROWS, N_Q>>>(out);
}

// round 17
// speedup vs baseline: 1.3404x; 1.0772x over previous
#include <cuda_runtime.h>
#include <cuda_bf16.h>
#include <cstdint>

// Problem constants
#define N_OBJ     32
#define N_GROUPS  4960      // C(32,3)
#define N_FILT    16
#define REL_DIM   16
#define BATCH     32
#define N_Q       512
#define FDIM      144       // 3*3*16
#define M_ROWS    512       // BATCH * N_FILT

// Split-bf16 segmented-K GEMM geometry
#define SEG       4992
#define KPAD      14976     // 3 * SEG = 234 * 64
#define KBLK      234
#define SPLITZ    9
#define CHUNKS    26        // KBLK / SPLITZ
#define CTA_M     128
#define CTA_N     128
#define BK        64
#define STAGES    3
#define STAGE_BYTES 32768
#define SMEM_TOTAL (STAGES * STAGE_BYTES)

// Scratch (no cudaMalloc allowed)
__device__ int            g_idxp[N_GROUPS];            // packed i|j<<8|k<<16
__device__ __nv_bfloat16  A3[(size_t)M_ROWS * KPAD];   // [m][k'] k'-major
__device__ __nv_bfloat16  B3[(size_t)N_Q * KPAD];      // [g][k'] k'-major
__device__ float          g_part[(size_t)SPLITZ * M_ROWS * N_Q];

// ---------------------------------------------------------------------------
// PTX helpers (family-safe: sm_80-era mma.sync / ldmatrix / cp.async)
// ---------------------------------------------------------------------------
__device__ __forceinline__ uint32_t smem_u32(const void* p) {
    uint32_t a;
    asm("{ .reg .u64 t; cvta.to.shared.u64 t, %1; cvt.u32.u64 %0, t; }"
        : "=r"(a) : "l"(p));
    return a;
}

__device__ __forceinline__ void cp_async16(uint32_t dst, const void* src) {
    asm volatile("cp.async.cg.shared.global [%0], [%1], 16;\n"
                 :: "r"(dst), "l"(src) : "memory");
}
#define CP_COMMIT() asm volatile("cp.async.commit_group;\n" ::: "memory")
#define CP_WAIT1()  asm volatile("cp.async.wait_group 1;\n" ::: "memory")
#define CP_WAIT0()  asm volatile("cp.async.wait_group 0;\n" ::: "memory")

__device__ __forceinline__ void ldsm_x4(uint32_t* r, uint32_t addr) {
    asm volatile("ldmatrix.sync.aligned.m8n8.x4.shared.b16 {%0,%1,%2,%3}, [%4];\n"
                 : "=r"(r[0]), "=r"(r[1]), "=r"(r[2]), "=r"(r[3]) : "r"(addr));
}

__device__ __forceinline__ void mma_16816(float* c, const uint32_t* a, const uint32_t* b) {
    asm volatile("mma.sync.aligned.m16n8k16.row.col.f32.bf16.bf16.f32 "
                 "{%0,%1,%2,%3}, {%4,%5,%6,%7}, {%8,%9}, {%0,%1,%2,%3};\n"
                 : "+f"(c[0]), "+f"(c[1]), "+f"(c[2]), "+f"(c[3])
                 : "r"(a[0]), "r"(a[1]), "r"(a[2]), "r"(a[3]), "r"(b[0]), "r"(b[1]));
}

// FFMA-only exp (x <= 0 expected; clamps at -87).
__device__ __forceinline__ float fast_exp(float x) {
    x = fmaxf(x, -87.0f);
    float t = x * 1.4426950408889634f;
    int ri = __float2int_rn(t);
    float f = t - (float)ri;
    float p = 1.8775767e-3f;
    p = fmaf(p, f, 8.9893397e-3f);
    p = fmaf(p, f, 5.5826318e-2f);
    p = fmaf(p, f, 2.4015361e-1f);
    p = fmaf(p, f, 6.9315308e-1f);
    p = fmaf(p, f, 1.0f);
    return p * __int_as_float((ri + 127) << 23);
}

// ---------------------------------------------------------------------------
// Kernel 0: unrank C(32,3) + zero segment padding of A3/B3
// ---------------------------------------------------------------------------
#define PAD_PER_ROW (3 * (SEG - N_GROUPS))    // 96
#define PAD_WORK    (512 * PAD_PER_ROW)       // 49152
__global__ void k_init() {
    int n = blockIdx.x * blockDim.x + threadIdx.x;
    if (n < N_GROUPS) {
        int rem = n, i = 0;
        for (; i < 30; i++) {
            int c = (31 - i) * (30 - i) / 2;
            if (rem < c) break;
            rem -= c;
        }
        int j = i + 1;
        for (; j < 31; j++) {
            int c = 31 - j;
            if (rem < c) break;
            rem -= c;
        }
        int k = j + 1 + rem;
        g_idxp[n] = i | (j << 8) | (k << 16);
    }
    if (n < PAD_WORK) {
        int r = n / PAD_PER_ROW;
        int q = n % PAD_PER_ROW;
        int seg = q / (SEG - N_GROUPS);
        int off = q % (SEG - N_GROUPS);
        size_t c = (size_t)seg * SEG + N_GROUPS + off;
        __nv_bfloat16 z = __float2bfloat16(0.f);
        A3[(size_t)r * KPAD + c] = z;
        B3[(size_t)r * KPAD + c] = z;
    }
}

// ---------------------------------------------------------------------------
// Kernel 1: rel_conv -> split-bf16 A3 rows (segmented: ah | ah | al).
// Transposed filters in smem ([pos][d][f], float4 broadcast reads);
// coalesced A3 stores.
// ---------------------------------------------------------------------------
__global__ void k_relconv(const float* __restrict__ inputs,
                          const float* __restrict__ filters) {
    __shared__ __align__(16) float filt_t[9 * 16 * 16];   // [pos][d][f]
    int tid = threadIdx.x;
    for (int t = tid; t < N_FILT * FDIM; t += blockDim.x) {
        int f = t / FDIM;
        int rem = t - f * FDIM;
        int pos = rem >> 4;
        int d = rem & 15;
        filt_t[pos * 256 + d * 16 + f] = filters[t];
    }
    __syncthreads();

    int n = blockIdx.x * blockDim.x + tid;
    int b = blockIdx.y;
    if (n >= N_GROUPS) return;

    int pk = g_idxp[n];
    int obj[3] = {pk & 255, (pk >> 8) & 255, pk >> 16};
    const float* base = inputs + (size_t)b * N_OBJ * N_OBJ * REL_DIM;

    float acc[16];
#pragma unroll
    for (int f = 0; f < 16; f++) acc[f] = 0.f;

#pragma unroll
    for (int ii = 0; ii < 3; ii++) {
#pragma unroll
        for (int jj = 0; jj < 3; jj++) {
            const float4* p = reinterpret_cast<const float4*>(
                base + (obj[ii] * N_OBJ + obj[jj]) * REL_DIM);
            float4 v0 = p[0], v1 = p[1], v2 = p[2], v3 = p[3];
            float xs[16] = {v0.x, v0.y, v0.z, v0.w, v1.x, v1.y, v1.z, v1.w,
                            v2.x, v2.y, v2.z, v2.w, v3.x, v3.y, v3.z, v3.w};
            const float4* ft = reinterpret_cast<const float4*>(&filt_t[(ii * 3 + jj) * 256]);
#pragma unroll
            for (int d = 0; d < 16; d++) {
                float x = xs[d];
                float4 f0 = ft[d * 4 + 0];
                float4 f1 = ft[d * 4 + 1];
                float4 f2 = ft[d * 4 + 2];
                float4 f3 = ft[d * 4 + 3];
                acc[0]  = fmaf(x, f0.x, acc[0]);  acc[1]  = fmaf(x, f0.y, acc[1]);
                acc[2]  = fmaf(x, f0.z, acc[2]);  acc[3]  = fmaf(x, f0.w, acc[3]);
                acc[4]  = fmaf(x, f1.x, acc[4]);  acc[5]  = fmaf(x, f1.y, acc[5]);
                acc[6]  = fmaf(x, f1.z, acc[6]);  acc[7]  = fmaf(x, f1.w, acc[7]);
                acc[8]  = fmaf(x, f2.x, acc[8]);  acc[9]  = fmaf(x, f2.y, acc[9]);
                acc[10] = fmaf(x, f2.z, acc[10]); acc[11] = fmaf(x, f2.w, acc[11]);
                acc[12] = fmaf(x, f3.x, acc[12]); acc[13] = fmaf(x, f3.y, acc[13]);
                acc[14] = fmaf(x, f3.z, acc[14]); acc[15] = fmaf(x, f3.w, acc[15]);
            }
        }
    }
#pragma unroll
    for (int f = 0; f < 16; f++) {
        __nv_bfloat16 hi = __float2bfloat16(acc[f]);
        __nv_bfloat16 lo = __float2bfloat16(acc[f] - __bfloat162float(hi));
        size_t row = (size_t)(b * 16 + f) * KPAD;
        A3[row + n]           = hi;
        A3[row + SEG + n]     = hi;
        A3[row + 2 * SEG + n] = lo;
    }
}

// ---------------------------------------------------------------------------
// Kernel 2: per-query softplus-product softmax -> split-bf16 B3 rows
// (segmented: bh | bl | bh).  Coalesced stores; exp on FMA pipe.
// ---------------------------------------------------------------------------
__global__ void k_weights(const float* __restrict__ logits) {
    int g = blockIdx.x;
    __shared__ float sp_s[N_OBJ];
    __shared__ float w_s[N_GROUPS];
    __shared__ float red_s[8];

    int tid = threadIdx.x;
    if (tid < N_OBJ) {
        float x = logits[g * N_OBJ + tid];
        sp_s[tid] = fmaxf(x, 0.f) + log1pf(expf(-fabsf(x)));
    }
    __syncthreads();

    float lmax = -1e30f;
    for (int n = tid; n < N_GROUPS; n += 256) {
        int pk = g_idxp[n];
        float w = sp_s[pk & 255] * sp_s[(pk >> 8) & 255] * sp_s[pk >> 16];
        w_s[n] = w;
        lmax = fmaxf(lmax, w);
    }
#pragma unroll
    for (int o = 16; o > 0; o >>= 1)
        lmax = fmaxf(lmax, __shfl_xor_sync(0xffffffffu, lmax, o));
    if ((tid & 31) == 0) red_s[tid >> 5] = lmax;
    __syncthreads();
    float bmax = red_s[0];
#pragma unroll
    for (int r = 1; r < 8; r++) bmax = fmaxf(bmax, red_s[r]);

    float lsum = 0.f;
    for (int n = tid; n < N_GROUPS; n += 256) {
        float e = fast_exp(w_s[n] - bmax);
        w_s[n] = e;
        lsum += e;
    }
#pragma unroll
    for (int o = 16; o > 0; o >>= 1)
        lsum += __shfl_xor_sync(0xffffffffu, lsum, o);
    __syncthreads();
    if ((tid & 31) == 0) red_s[tid >> 5] = lsum;
    __syncthreads();
    float bsum = 0.f;
#pragma unroll
    for (int r = 0; r < 8; r++) bsum += red_s[r];
    float inv = 1.f / bsum;

    size_t row = (size_t)g * KPAD;
    for (int n = tid; n < N_GROUPS; n += 256) {
        float v = w_s[n] * inv;
        __nv_bfloat16 hi = __float2bfloat16(v);
        __nv_bfloat16 lo = __float2bfloat16(v - __bfloat162float(hi));
        B3[row + n]           = hi;
        B3[row + SEG + n]     = lo;
        B3[row + 2 * SEG + n] = hi;
    }
}

// ---------------------------------------------------------------------------
// Kernel 3: HMMA bf16 GEMM  part[z][m][g] = sum_{k' in split} A3[m][k']*B3[g][k']
// CTA 128x128, warp 32x64, BK=64 swizzled, cp.async 3-stage, split-K Z=9.
// (Exact known-good 25.5us configuration.)
// ---------------------------------------------------------------------------
__global__ void __launch_bounds__(256) k_mma() {
    extern __shared__ char smem[];
    const uint32_t sbase = smem_u32(smem);
    int tid = threadIdx.x;
    int lane = tid & 31;
    int wid = tid >> 5;
    int wm = wid & 3;
    int wn = wid >> 2;
    int m0 = blockIdx.y * CTA_M;
    int n0 = blockIdx.x * CTA_N;
    int kb0 = blockIdx.z * CHUNKS;

    int seg_r[4], seg_c[4];
#pragma unroll
    for (int i = 0; i < 4; i++) {
        int seg = tid + i * 256;
        seg_r[i] = seg >> 3;
        seg_c[i] = seg & 7;
    }

    float acc[2][8][4];
#pragma unroll
    for (int mt = 0; mt < 2; mt++)
#pragma unroll
        for (int nt = 0; nt < 8; nt++)
#pragma unroll
            for (int q = 0; q < 4; q++) acc[mt][nt][q] = 0.f;

#pragma unroll
    for (int pc = 0; pc < 2; pc++) {
        uint32_t abase = sbase + pc * STAGE_BYTES;
        uint32_t bbase = abase + 16384;
        size_t kelem = (size_t)(kb0 + pc) * BK;
#pragma unroll
        for (int i = 0; i < 4; i++) {
            int r = seg_r[i], c = seg_c[i];
            uint32_t swo = (uint32_t)(r * 128 + ((c ^ (r & 7)) << 4));
            cp_async16(abase + swo, A3 + (size_t)(m0 + r) * KPAD + kelem + c * 8);
            cp_async16(bbase + swo, B3 + (size_t)(n0 + r) * KPAD + kelem + c * 8);
        }
        CP_COMMIT();
    }

    for (int kc = 0; kc < CHUNKS; kc++) {
        int stg = kc % STAGES;
        CP_WAIT1();
        __syncthreads();

        if (kc + 2 < CHUNKS) {
            int ps = (kc + 2) % STAGES;
            uint32_t abase = sbase + ps * STAGE_BYTES;
            uint32_t bbase = abase + 16384;
            size_t kelem = (size_t)(kb0 + kc + 2) * BK;
#pragma unroll
            for (int i = 0; i < 4; i++) {
                int r = seg_r[i], c = seg_c[i];
                uint32_t swo = (uint32_t)(r * 128 + ((c ^ (r & 7)) << 4));
                cp_async16(abase + swo, A3 + (size_t)(m0 + r) * KPAD + kelem + c * 8);
                cp_async16(bbase + swo, B3 + (size_t)(n0 + r) * KPAD + kelem + c * 8);
            }
        }
        CP_COMMIT();

        uint32_t abase = sbase + stg * STAGE_BYTES;
        uint32_t bbase = abase + 16384;
#pragma unroll
        for (int ks = 0; ks < 4; ks++) {
            int t = lane >> 3, rw = lane & 7;
            uint32_t a[2][4];
#pragma unroll
            for (int mt = 0; mt < 2; mt++) {
                int m = wm * 32 + mt * 16 + ((t & 1) ? 8 : 0) + rw;
                int c = ks * 2 + (t >> 1);
                ldsm_x4(a[mt], abase + m * 128 + ((c ^ (m & 7)) << 4));
            }
            uint32_t b[8][2];
#pragma unroll
            for (int np = 0; np < 4; np++) {
                int n = wn * 64 + np * 16 + ((t & 2) ? 8 : 0) + rw;
                int c = ks * 2 + (t & 1);
                uint32_t r4[4];
                ldsm_x4(r4, bbase + n * 128 + ((c ^ (n & 7)) << 4));
                b[np * 2 + 0][0] = r4[0]; b[np * 2 + 0][1] = r4[1];
                b[np * 2 + 1][0] = r4[2]; b[np * 2 + 1][1] = r4[3];
            }
#pragma unroll
            for (int mt = 0; mt < 2; mt++)
#pragma unroll
                for (int nt = 0; nt < 8; nt++)
                    mma_16816(acc[mt][nt], a[mt], b[nt]);
        }
    }
    CP_WAIT0();

    float* base = g_part + (size_t)blockIdx.z * (M_ROWS * N_Q);
    int gr = lane >> 2, gc = (lane & 3) * 2;
#pragma unroll
    for (int mt = 0; mt < 2; mt++) {
#pragma unroll
        for (int nt = 0; nt < 8; nt++) {
            int row = m0 + wm * 32 + mt * 16 + gr;
            int col = n0 + wn * 64 + nt * 8 + gc;
            *reinterpret_cast<float2*>(&base[(size_t)row * N_Q + col]) =
                make_float2(acc[mt][nt][0], acc[mt][nt][1]);
            *reinterpret_cast<float2*>(&base[(size_t)(row + 8) * N_Q + col]) =
                make_float2(acc[mt][nt][2], acc[mt][nt][3]);
        }
    }
}

// ---------------------------------------------------------------------------
// Kernel 4: reduce split-K partials with smem transpose.
// Block = (b, 128-g chunk).  Phase 1: float4 loads along g (coalesced, MLP=9).
// Phase 2: float4 stores along (g,f) (fully coalesced).
// ---------------------------------------------------------------------------
__global__ void __launch_bounds__(512) k_reduce(float* __restrict__ out) {
    __shared__ float tile[16][132];
    int t = threadIdx.x;           // 0..511
    int b = blockIdx.y;
    int g0 = blockIdx.x * 128;

    // Phase 1: 16 f-rows x 32 float4 g-cols = 512 work items (one per thread)
    {
        int f = t >> 5;            // 0..15
        int gq = t & 31;           // float4 index along g
        const float* src = g_part + (size_t)(b * 16 + f) * N_Q + g0 + gq * 4;
        float4 s = make_float4(0.f, 0.f, 0.f, 0.f);
#pragma unroll
        for (int z = 0; z < SPLITZ; z++) {
            float4 v = *reinterpret_cast<const float4*>(src + (size_t)z * (M_ROWS * N_Q));
            s.x += v.x; s.y += v.y; s.z += v.z; s.w += v.w;
        }
        tile[f][gq * 4 + 0] = s.x;
        tile[f][gq * 4 + 1] = s.y;
        tile[f][gq * 4 + 2] = s.z;
        tile[f][gq * 4 + 3] = s.w;
    }
    __syncthreads();

    // Phase 2: 128 g x 4 f-quads = 512 float4 outputs (one per thread)
    {
        int gl = t >> 2;           // 0..127
        int fq = (t & 3) * 4;      // 0,4,8,12
        float4 v = make_float4(tile[fq + 0][gl], tile[fq + 1][gl],
                               tile[fq + 2][gl], tile[fq + 3][gl]);
        *reinterpret_cast<float4*>(
            out + ((size_t)b * N_Q + g0 + gl) * N_FILT + fq) = v;
    }
}

// ---------------------------------------------------------------------------
extern "C" void kernel_launch(void* const* d_in, const int* in_sizes, int n_in,
                              void* d_out, int out_size) {
    const float* inputs  = (const float*)d_in[0];   // (32,32,32,16) fp32
    const float* logits  = (const float*)d_in[1];   // (512,32) fp32
    const float* filters = (const float*)d_in[2];   // (16,3,3,16) fp32
    float* out = (float*)d_out;                     // (32,512,16) fp32
    (void)in_sizes; (void)n_in; (void)out_size;

    cudaFuncSetAttribute(k_mma, cudaFuncAttributeMaxDynamicSharedMemorySize, SMEM_TOTAL);

    k_init<<<(PAD_WORK + 255) / 256, 256>>>();
    k_relconv<<<dim3((N_GROUPS + 127) / 128, BATCH), 128>>>(inputs, filters);
    k_weights<<<N_Q, 256>>>(logits);
    k_mma<<<dim3(N_Q / CTA_N, M_ROWS / CTA_M, SPLITZ), 256, SMEM_TOTAL>>>();
    k_reduce<<<dim3(N_Q / 128, BATCH), 512>>>(out);
}